// round 2
// baseline (speedup 1.0000x reference)
#include <cuda_runtime.h>
#include <cstdint>

#define BQ     32
#define NKEYS  4096
#define DIM    64
#define NQ     8
#define CPB    8          // chunks per batch -> grid 256
#define CHUNK  512
#define TILE   64
#define NTILES 8
#define KPAD   68         // padded row stride (floats)

// ---- scratch (no allocations allowed) ----
__device__ float    g_pv[BQ * CPB * NQ * DIM];   // partial PV sums
__device__ float    g_cs[BQ * CPB * NQ];         // partial column sums
__device__ unsigned g_cnt[BQ];                    // last-block counters (zero-init)

// ---- cp.async helpers ----
__device__ __forceinline__ void cp16(uint32_t s, const float* g) {
    asm volatile("cp.async.cg.shared.global [%0], [%1], 16;\n" :: "r"(s), "l"(g));
}
__device__ __forceinline__ void cp_commit() {
    asm volatile("cp.async.commit_group;\n" ::: "memory");
}
template <int N>
__device__ __forceinline__ void cp_wait() {
    asm volatile("cp.async.wait_group %0;\n" :: "n"(N) : "memory");
}

// ---- smem layout (float offsets) ----
#define OFF_Q   0
#define Q_SZ    (NQ * KPAD)                 // 544
#define OFF_K   (OFF_Q + Q_SZ)              // 544
#define KS_SZ   (TILE * KPAD)               // 4352
#define OFF_V   (OFF_K + 2 * KS_SZ)         // 9248
#define OFF_P   (OFF_V + 2 * KS_SZ)         // 17952
#define OFF_PV  (OFF_P + TILE * NQ)         // 18464
#define OFF_WS  (OFF_PV + 2048)             // 20512
#define SMEM_FLOATS (OFF_WS + 64)           // 20576 -> 82,304 bytes

extern __shared__ float smem[];

__global__ __launch_bounds__(256, 2)
void attn_fused(const float* __restrict__ keys,
                const float* __restrict__ vals,
                const float* __restrict__ query,
                float* __restrict__ out) {
    const int tid   = threadIdx.x;
    const int b     = blockIdx.x >> 3;
    const int chunk = blockIdx.x & 7;
    const int n0    = chunk * CHUNK;
    const uint32_t sbase = (uint32_t)__cvta_generic_to_shared(smem);
    __shared__ int s_last;

    const float* kg0 = keys + ((size_t)b * NKEYS + n0) * DIM;
    const float* vg0 = vals + ((size_t)b * NKEYS + n0) * DIM;

    // ---- prefetch tile 0 (64 rows x 64 floats, K and V) ----
    {
#pragma unroll
        for (int i = 0; i < 4; ++i) {
            int c = tid + i * 256;              // 0..1023 float4 chunks
            int r = c >> 4, s = (c & 15) << 2;
            cp16(sbase + (uint32_t)((OFF_K + r * KPAD + s) << 2), kg0 + r * DIM + s);
            cp16(sbase + (uint32_t)((OFF_V + r * KPAD + s) << 2), vg0 + r * DIM + s);
        }
        cp_commit();
    }

    // ---- load query (8 x 64) ----
    if (tid < 128) {
        int r = tid >> 4, s = (tid & 15) << 2;
        *(float4*)&smem[OFF_Q + r * KPAD + s] =
            *(const float4*)(query + ((size_t)b * NQ + r) * DIM + s);
    }

    const int lane = tid & 31;
    const int warp = tid >> 5;
    const int k_qk = tid >> 2;          // QK: key index within tile (0..63)
    const int m0   = (tid & 3) << 1;    // QK: query pair (0,2,4,6)
    const int m0p  = (warp & 1) * 4;    // PV: query group per warp
    const int kq   = warp >> 1;         // PV: key 16-block per warp

    float cs0 = 0.f, cs1 = 0.f;
    float pv00 = 0.f, pv01 = 0.f, pv10 = 0.f, pv11 = 0.f;
    float pv20 = 0.f, pv21 = 0.f, pv30 = 0.f, pv31 = 0.f;

    for (int t = 0; t < NTILES; ++t) {
        const int buf = t & 1;
        if (t + 1 < NTILES) {
            const int nb = (t + 1) & 1;
            const float* kg = kg0 + (size_t)(t + 1) * TILE * DIM;
            const float* vg = vg0 + (size_t)(t + 1) * TILE * DIM;
#pragma unroll
            for (int i = 0; i < 4; ++i) {
                int c = tid + i * 256;
                int r = c >> 4, s = (c & 15) << 2;
                cp16(sbase + (uint32_t)((OFF_K + nb * KS_SZ + r * KPAD + s) << 2), kg + r * DIM + s);
                cp16(sbase + (uint32_t)((OFF_V + nb * KS_SZ + r * KPAD + s) << 2), vg + r * DIM + s);
            }
            cp_commit();
            cp_wait<1>();
        } else {
            cp_wait<0>();
        }
        __syncthreads();

        // ---------- QK + per-key softmax over the 8 queries ----------
        {
            const float* kb = &smem[OFF_K + buf * KS_SZ + k_qk * KPAD];
            float a0 = 0.f, a1 = 0.f;
#pragma unroll
            for (int d4 = 0; d4 < 16; ++d4) {
                float4 kv = *(const float4*)(kb + (d4 << 2));
                float4 q0 = *(const float4*)&smem[OFF_Q + (m0 + 0) * KPAD + (d4 << 2)];
                float4 q1 = *(const float4*)&smem[OFF_Q + (m0 + 1) * KPAD + (d4 << 2)];
                a0 += kv.x * q0.x + kv.y * q0.y + kv.z * q0.z + kv.w * q0.w;
                a1 += kv.x * q1.x + kv.y * q1.y + kv.z * q1.z + kv.w * q1.w;
            }
            a0 *= 0.125f; a1 *= 0.125f;

            float mx = fmaxf(a0, a1);
            mx = fmaxf(mx, __shfl_xor_sync(0xffffffffu, mx, 1));
            mx = fmaxf(mx, __shfl_xor_sync(0xffffffffu, mx, 2));
            float e0 = __expf(a0 - mx), e1 = __expf(a1 - mx);
            float sum = e0 + e1;
            sum += __shfl_xor_sync(0xffffffffu, sum, 1);
            sum += __shfl_xor_sync(0xffffffffu, sum, 2);
            float inv = 1.0f / sum;
            float p0 = e0 * inv + 1e-8f;
            float p1 = e1 * inv + 1e-8f;
            *(float2*)&smem[OFF_P + k_qk * NQ + m0] = make_float2(p0, p1);
            cs0 += p0; cs1 += p1;
        }
        __syncthreads();

        // ---------- PV accumulate (rank-1 updates in registers) ----------
        {
            const float* vb = &smem[OFF_V + buf * KS_SZ];
#pragma unroll
            for (int kk = 0; kk < 16; ++kk) {
                int k = kq * 16 + kk;
                float4 pk = *(const float4*)&smem[OFF_P + k * NQ + m0p];  // warp-uniform broadcast
                float2 vv = *(const float2*)(vb + k * KPAD + (lane << 1));
                pv00 += pk.x * vv.x; pv01 += pk.x * vv.y;
                pv10 += pk.y * vv.x; pv11 += pk.y * vv.y;
                pv20 += pk.z * vv.x; pv21 += pk.z * vv.y;
                pv30 += pk.w * vv.x; pv31 += pk.w * vv.y;
            }
        }
        __syncthreads();
    }

    // ---------- colsum reduce (lanes with same (lane&3) share the query pair) ----------
#pragma unroll
    for (int off = 16; off >= 4; off >>= 1) {
        cs0 += __shfl_xor_sync(0xffffffffu, cs0, off);
        cs1 += __shfl_xor_sync(0xffffffffu, cs1, off);
    }
    if (lane < 4) {
        smem[OFF_WS + warp * 8 + lane * 2 + 0] = cs0;
        smem[OFF_WS + warp * 8 + lane * 2 + 1] = cs1;
    }
    // ---------- PV partials to smem ----------
    {
        int l2 = lane << 1;
        smem[OFF_PV + (warp * 4 + 0) * 64 + l2]     = pv00;
        smem[OFF_PV + (warp * 4 + 0) * 64 + l2 + 1] = pv01;
        smem[OFF_PV + (warp * 4 + 1) * 64 + l2]     = pv10;
        smem[OFF_PV + (warp * 4 + 1) * 64 + l2 + 1] = pv11;
        smem[OFF_PV + (warp * 4 + 2) * 64 + l2]     = pv20;
        smem[OFF_PV + (warp * 4 + 2) * 64 + l2 + 1] = pv21;
        smem[OFF_PV + (warp * 4 + 3) * 64 + l2]     = pv30;
        smem[OFF_PV + (warp * 4 + 3) * 64 + l2 + 1] = pv31;
    }
    __syncthreads();

    if (tid < 8) {
        float s = 0.f;
#pragma unroll
        for (int w = 0; w < 8; ++w) s += smem[OFF_WS + w * 8 + tid];
        g_cs[(b * CPB + chunk) * NQ + tid] = s;
    }
    {
        int m = tid >> 5, v = tid & 31;
        int mg = (m >> 2), j = m & 3;
        float s1 = 0.f, s2 = 0.f;
#pragma unroll
        for (int q = 0; q < 4; ++q) {
            int w = q * 2 + mg;
            s1 += smem[OFF_PV + (w * 4 + j) * 64 + v];
            s2 += smem[OFF_PV + (w * 4 + j) * 64 + v + 32];
        }
        float* dst = &g_pv[((size_t)(b * CPB + chunk) * NQ + m) * DIM];
        dst[v]      = s1;
        dst[v + 32] = s2;
    }

    // ---------- fused finalize: last chunk CTA of this batch reduces ----------
    __syncthreads();
    if (tid == 0) {
        __threadfence();
        unsigned old = atomicAdd(&g_cnt[b], 1u);
        s_last = (old == CPB - 1) ? 1 : 0;
    }
    __syncthreads();
    if (s_last) {
        __threadfence();
#pragma unroll
        for (int idx = tid; idx < NQ * DIM; idx += 256) {
            int m = idx >> 6, v = idx & 63;
            float cs = 0.f, pv = 0.f;
#pragma unroll
            for (int c = 0; c < CPB; ++c) {
                cs += g_cs[(b * CPB + c) * NQ + m];
                pv += g_pv[((size_t)(b * CPB + c) * NQ + m) * DIM + v];
            }
            out[(size_t)b * NQ * DIM + idx] = pv / cs;
        }
        if (tid == 0) g_cnt[b] = 0;   // reset for next graph replay
    }
}

extern "C" void kernel_launch(void* const* d_in, const int* in_sizes, int n_in,
                              void* d_out, int out_size) {
    const float* keys  = (const float*)d_in[0];
    const float* vals  = (const float*)d_in[1];
    const float* query = (const float*)d_in[2];
    float* out = (float*)d_out;

    cudaFuncSetAttribute(attn_fused,
                         cudaFuncAttributeMaxDynamicSharedMemorySize,
                         SMEM_FLOATS * sizeof(float));
    attn_fused<<<BQ * CPB, 256, SMEM_FLOATS * sizeof(float)>>>(keys, vals, query, out);
}